// round 14
// baseline (speedup 1.0000x reference)
#include <cuda_runtime.h>
#include <cuda_fp16.h>
#include <cstdint>

typedef unsigned long long u64;
typedef uint32_t u32;

#define MAXN 50176
#define MAXE 800000

__device__ float4 g_t4[(size_t)MAXN * 32];    // layer-2 pre-BN output [N,128] fp32
__device__ u32 g_x16[(size_t)MAXN * 64];      // x  as fp16 pairs [N][64]
__device__ u32 g_h16[(size_t)MAXN * 64];      // h1 as fp16 pairs [N][64]
__device__ __align__(16) float g_sum[2][128];
__device__ __align__(16) float g_sq[2][128];
__device__ int g_idx64;
__device__ int g_cnt[MAXN];
__device__ int g_rowptr[MAXN + 1];
__device__ int g_cursor[MAXN];
__device__ int g_adj[MAXE];
// decoupled-lookback scan state + grid barrier state (re-zeroed each launch)
__device__ volatile int g_sstat[64];
__device__ volatile int g_sagg[64];
__device__ volatile int g_sinc[64];
__device__ int g_barcnt;
__device__ volatile int g_barrel;
// W fragments (mma B-operand layout), fp16 pairs, per layer.
__device__ __align__(16) u32 g_wf[2][8192];

// ===========================================================================
// Edge index accessors
// ===========================================================================
__device__ __forceinline__ int edge_src(const void* eidx, int E, int e) {
    if (g_idx64) return (int)((const long long*)eidx)[e];
    return ((const int*)eidx)[e];
}
__device__ __forceinline__ int edge_dst(const void* eidx, int E, int e) {
    if (g_idx64) return (int)((const long long*)eidx)[(size_t)E + e];
    return ((const int*)eidx)[E + e];
}

// ===========================================================================
// K1: combined init + prep.
// blocks [0,64):      W^T -> fp16 mma B-fragments
// block 64:           dtype detect + zero BN sums + zero scan/barrier state
// blocks [64,64+xblk): x -> fp16 (and zero g_cnt for idx < N)
// ===========================================================================
__global__ void __launch_bounds__(256) prep_kernel(const float* __restrict__ W1,
                                                   const float* __restrict__ W2,
                                                   const float* __restrict__ x,
                                                   const int* __restrict__ w,
                                                   int E, int N) {
    int b = blockIdx.x, t = threadIdx.x;
    if (b < 64) {
        int i = b * 256 + t;            // 0..16383
        int l = i >> 13;
        int j = i & 8191;
        int n = j & 127;                // coalesced over n
        int k = (j >> 7) * 2;
        const float* W = l ? W2 : W1;
        float v0 = W[k * 128 + n];
        float v1 = W[(k + 1) * 128 + n];
        __half2 p = __float22half2_rn(make_float2(v0, v1));
        int idx = ((((n >> 3) * 8) + (k >> 4)) * 32 + (n & 7) * 4 + ((k & 7) >> 1)) * 2
                  + ((k >> 3) & 1);
        g_wf[l][idx] = *(u32*)&p;
        return;
    }
    int j = (b - 64) * 256 + t;         // u32 output index over N*64
    if (j < N * 64) {
        float2 v = *(const float2*)(x + (size_t)j * 2);
        __half2 p = __float22half2_rn(v);
        g_x16[j] = *(u32*)&p;
    }
    if (j < N) g_cnt[j] = 0;
    if (b == 64) {
        __shared__ int any;
        if (t == 0) any = 0;
        __syncthreads();
        int limit = 2 * E; if (limit > 8192) limit = 8192;
        for (int q = 1 + 2 * t; q < limit; q += 512)
            if (w[q] != 0) any = 1;
        __syncthreads();
        if (t == 0) { g_idx64 = (any == 0) ? 1 : 0; g_barcnt = 0; g_barrel = 0; }
        if (t < 128) {
            g_sum[0][t] = 0.f; g_sum[1][t] = 0.f;
            g_sq[0][t]  = 0.f; g_sq[1][t]  = 0.f;
        }
        if (t < 64) { g_sstat[t] = 0; g_sagg[t] = 0; g_sinc[t] = 0; }
    }
}

// ===========================================================================
// K2: histogram of dst.
// ===========================================================================
__global__ void __launch_bounds__(256) hist_kernel(const void* __restrict__ eidx, int E) {
    int e = blockIdx.x * 256 + threadIdx.x;
    if (e < E) atomicAdd(&g_cnt[edge_dst(eidx, E, e)], 1);
}

// ===========================================================================
// K3: single-pass exclusive scan (decoupled lookback) -> rowptr + cursor.
// ===========================================================================
#define SCAN_T 256
#define SCAN_E 4
#define SCAN_B (SCAN_T * SCAN_E)

__global__ void __launch_bounds__(SCAN_T) scan_kernel(int N) {
    __shared__ int sh[SCAN_T];
    __shared__ int s_prefix;
    int b = blockIdx.x, t = threadIdx.x;
    int base = b * SCAN_B + t * SCAN_E;
    int v[SCAN_E];
    int s = 0;
#pragma unroll
    for (int i = 0; i < SCAN_E; i++) {
        v[i] = (base + i < N) ? g_cnt[base + i] : 0;
        s += v[i];
    }
    sh[t] = s;
    __syncthreads();
    for (int off = 1; off < SCAN_T; off <<= 1) {
        int u = 0;
        if (t >= off) u = sh[t - off];
        __syncthreads();
        if (t >= off) sh[t] += u;
        __syncthreads();
    }
    int total = sh[SCAN_T - 1];
    int lrun = (t == 0) ? 0 : sh[t - 1];

    if (t == 0) {
        if (b == 0) {
            g_sinc[0] = total;
            __threadfence();
            g_sstat[0] = 2;
            s_prefix = 0;
        } else {
            g_sagg[b] = total;
            __threadfence();
            g_sstat[b] = 1;
            int prefix = 0;
            int idx = b - 1;
            while (true) {
                int st = g_sstat[idx];
                if (st == 2) { prefix += g_sinc[idx]; break; }
                if (st == 1) { prefix += g_sagg[idx]; idx--; }
            }
            g_sinc[b] = prefix + total;
            __threadfence();
            g_sstat[b] = 2;
            s_prefix = prefix;
        }
    }
    __syncthreads();
    int run = s_prefix + lrun;
#pragma unroll
    for (int i = 0; i < SCAN_E; i++) {
        if (base + i <= N) {
            g_rowptr[base + i] = run;
            if (base + i < N) g_cursor[base + i] = run;
        }
        run += v[i];
    }
}

// ===========================================================================
// K4: CSR fill.
// ===========================================================================
__global__ void __launch_bounds__(256) fill_kernel(const void* __restrict__ eidx, int E) {
    int e = blockIdx.x * 256 + threadIdx.x;
    if (e >= E) return;
    int d = edge_dst(eidx, E, e);
    int s = edge_src(eidx, E, e);
    int pos = atomicAdd(&g_cursor[d], 1);
    g_adj[pos] = s;
}

// ===========================================================================
// Grid barrier (cumulative count; all launched CTAs participate).
// ===========================================================================
__device__ __forceinline__ void grid_barrier(int phase, int ncta) {
    __syncthreads();
    __threadfence();
    if (threadIdx.x == 0) {
        int v = atomicAdd(&g_barcnt, 1);
        if (v == ncta * phase - 1) g_barrel = phase;
        while (g_barrel < phase) { }
    }
    __syncthreads();
    __threadfence();
}

// ===========================================================================
// A fragment slot for row r (0..63), even col k (0..126)
// ===========================================================================
__device__ __forceinline__ int a_fragidx(int r, int k) {
    return (((r >> 4) * 8 + (k >> 4)) * 32 + (r & 7) * 4 + ((k & 7) >> 1)) * 4
           + ((k >> 3) & 1) * 2 + ((r >> 3) & 1);
}

// ===========================================================================
// K5: mega-fused persistent kernel: layer1 -> barrier -> layer2 -> barrier
// -> BN apply. 512 threads, 2 CTAs/SM, 64-row tiles.
// ===========================================================================
#define SM_SSUM 0
#define SM_SSQ  512
#define SM_SC   1024
#define SM_SH   1536
#define SM_A    2048
#define SM_B    (2048 + 16384)
#define GEMM_SMEM_TOTAL (2048 + 16384 + 32768)

__device__ __forceinline__ void mma_f16(float* c, const u32* a, const u32* b) {
    asm volatile(
        "mma.sync.aligned.m16n8k16.row.col.f32.f16.f16.f32 "
        "{%0,%1,%2,%3}, {%4,%5,%6,%7}, {%8,%9}, {%0,%1,%2,%3};"
        : "+f"(c[0]), "+f"(c[1]), "+f"(c[2]), "+f"(c[3])
        : "r"(a[0]), "r"(a[1]), "r"(a[2]), "r"(a[3]), "r"(b[0]), "r"(b[1]));
}

__device__ __forceinline__ void acc_u2(float4& acc, uint2 u) {
    float2 f0 = __half22float2(*(__half2*)&u.x);
    float2 f1 = __half22float2(*(__half2*)&u.y);
    acc.x += f0.x; acc.y += f0.y; acc.z += f1.x; acc.w += f1.y;
}

// One GIN layer over all tiles assigned to this CTA.
template <int LAYER>
__device__ void do_layer(char* smem, const float* __restrict__ bias,
                         bool bn_in,    // apply sc/sh (from smem) to gathered input
                         int N, int ntiles) {
    float* s_sum = (float*)(smem + SM_SSUM);
    float* s_sq  = (float*)(smem + SM_SSQ);
    float* s_sc  = (float*)(smem + SM_SC);
    float* s_sh  = (float*)(smem + SM_SH);
    u32* AF = (u32*)(smem + SM_A);
    u32* BF = (u32*)(smem + SM_B);

    int tid = threadIdx.x, wid = tid >> 5, lane = tid & 31;
    const u32* base = LAYER ? g_h16 : g_x16;

    // B fragments for this layer
    {
        const float4* sf = (const float4*)g_wf[LAYER];
        float4* df = (float4*)BF;
        for (int p = tid; p < 2048; p += 512) df[p] = sf[p];
    }
    __syncthreads();

    float4 sc4, sh4;
    if (bn_in) {
        sc4 = *(const float4*)&s_sc[lane * 4];
        sh4 = *(const float4*)&s_sh[lane * 4];
    }

    int wm = wid & 3, wn = wid >> 2;
    int g = lane >> 2, tig = lane & 3;

    for (int tile = blockIdx.x; tile < ntiles; tile += gridDim.x) {
        int row0 = tile * 64;
        if (tid < 128) { s_sum[tid] = 0.f; s_sq[tid] = 0.f; }

        // ---- Gather + fragment conversion: warp handles 4 rows ----
#pragma unroll 1
        for (int ni = 0; ni < 4; ni++) {
            int r = wid * 4 + ni;
            int gr = row0 + r;
            float4 acc = make_float4(0.f, 0.f, 0.f, 0.f);
            float cnt = 0.f;
            if (gr < N) {
                acc_u2(acc, *(const uint2*)(base + (size_t)gr * 64 + lane * 2));
                int start = g_rowptr[gr];
                int end   = g_rowptr[gr + 1];
                cnt = (float)(end - start + 1);
                for (int j0 = start; j0 < end; j0 += 32) {
                    int n = end - j0; if (n > 32) n = 32;
                    int myIdx = (lane < n) ? g_adj[j0 + lane] : 0;
                    int k = 0;
                    for (; k + 8 <= n; k += 8) {
                        uint2 u[8];
#pragma unroll
                        for (int q = 0; q < 8; q++) {
                            int nb = __shfl_sync(0xffffffffu, myIdx, k + q);
                            u[q] = *(const uint2*)(base + (size_t)nb * 64 + lane * 2);
                        }
#pragma unroll
                        for (int q = 0; q < 8; q++) acc_u2(acc, u[q]);
                    }
                    for (; k < n; k++) {
                        int nb = __shfl_sync(0xffffffffu, myIdx, k);
                        acc_u2(acc, *(const uint2*)(base + (size_t)nb * 64 + lane * 2));
                    }
                }
            }
            float4 tv;
            if (bn_in) {
                tv.x = fmaf(acc.x, sc4.x, cnt * sh4.x);
                tv.y = fmaf(acc.y, sc4.y, cnt * sh4.y);
                tv.z = fmaf(acc.z, sc4.z, cnt * sh4.z);
                tv.w = fmaf(acc.w, sc4.w, cnt * sh4.w);
            } else {
                tv = acc;
            }
            __half2 p0 = __float22half2_rn(make_float2(tv.x, tv.y));
            __half2 p1 = __float22half2_rn(make_float2(tv.z, tv.w));
            int k0 = lane * 4;
            AF[a_fragidx(r, k0)]     = *(u32*)&p0;
            AF[a_fragidx(r, k0 + 2)] = *(u32*)&p1;
        }
        __syncthreads();

        // ---- MMA: warp tile 16 rows (wm) x 32 cols (wn quarter) ----
        float acc[4][4];
#pragma unroll
        for (int n = 0; n < 4; n++)
#pragma unroll
            for (int q = 0; q < 4; q++) acc[n][q] = 0.f;

#pragma unroll
        for (int kt = 0; kt < 8; kt++) {
            u32 ah[4];
            {
                int bq = ((wm * 8 + kt) * 32 + lane) * 4;
                *(uint4*)ah = *(const uint4*)(AF + bq);
            }
#pragma unroll
            for (int n = 0; n < 4; n++) {
                u32 bf[2];
                int bq = (((wn * 4 + n) * 8 + kt) * 32 + lane) * 2;
                *(uint2*)bf = *(const uint2*)(BF + bq);
                mma_f16(acc[n], ah, bf);
            }
        }

        // ---- Epilogue: bias + relu + store + BN stats ----
#pragma unroll
        for (int n = 0; n < 4; n++) {
            int cbase = wn * 32 + n * 8 + tig * 2;
            float2 bb = *(const float2*)(bias + cbase);
            float s0 = 0.f, s1 = 0.f, q0 = 0.f, q1 = 0.f;
            int rb = row0 + wm * 16 + g;
#pragma unroll
            for (int rh = 0; rh < 2; rh++) {
                int gr = rb + rh * 8;
                float h0 = fmaxf(acc[n][rh * 2 + 0] + bb.x, 0.f);
                float h1 = fmaxf(acc[n][rh * 2 + 1] + bb.y, 0.f);
                if (gr < N) {
                    if (LAYER == 0) {
                        __half2 hq = __float22half2_rn(make_float2(h0, h1));
                        g_h16[(size_t)gr * 64 + (cbase >> 1)] = *(u32*)&hq;
                        float2 hf = __half22float2(hq);
                        h0 = hf.x; h1 = hf.y;   // stats on quantized values
                    } else {
                        *(float2*)((float*)g_t4 + (size_t)gr * 128 + cbase) =
                            make_float2(h0, h1);
                    }
                    s0 += h0; s1 += h1;
                    q0 += h0 * h0; q1 += h1 * h1;
                }
            }
#pragma unroll
            for (int o = 4; o < 32; o <<= 1) {
                s0 += __shfl_xor_sync(0xffffffffu, s0, o);
                s1 += __shfl_xor_sync(0xffffffffu, s1, o);
                q0 += __shfl_xor_sync(0xffffffffu, q0, o);
                q1 += __shfl_xor_sync(0xffffffffu, q1, o);
            }
            if (g == 0) {
                atomicAdd(&s_sum[cbase], s0);
                atomicAdd(&s_sum[cbase + 1], s1);
                atomicAdd(&s_sq[cbase], q0);
                atomicAdd(&s_sq[cbase + 1], q1);
            }
        }

        __syncthreads();
        if (tid < 128) {
            atomicAdd(&g_sum[LAYER][tid], s_sum[tid]);
            atomicAdd(&g_sq[LAYER][tid], s_sq[tid]);
        }
        __syncthreads();
    }
}

__global__ void __launch_bounds__(512, 2) fused_all_kernel(
        const float* __restrict__ b1, const float* __restrict__ b2,
        const float* __restrict__ g1, const float* __restrict__ be1,
        const float* __restrict__ g2, const float* __restrict__ be2,
        float4* __restrict__ dst,
        float invN, int N, int ntiles, int n4) {
    extern __shared__ char smem[];
    float* s_sc = (float*)(smem + SM_SC);
    float* s_sh = (float*)(smem + SM_SH);
    int tid = threadIdx.x;
    int ncta = gridDim.x;

    // ---- Layer 1: gather(x16) + GEMM -> g_h16 + stats[0] ----
    do_layer<0>(smem, b1, false, N, ntiles);

    grid_barrier(1, ncta);

    // ---- BN(0) coefficients ----
    if (tid < 128) {
        float m = g_sum[0][tid] * invN;
        float var = g_sq[0][tid] * invN - m * m;
        float s = g1[tid] * rsqrtf(var + 1e-5f);
        s_sc[tid] = s;
        s_sh[tid] = be1[tid] - m * s;
    }
    __syncthreads();

    // ---- Layer 2: BN0-folded gather(g_h16) + GEMM -> g_t4 + stats[1] ----
    do_layer<1>(smem, b2, true, N, ntiles);

    grid_barrier(2, ncta);

    // ---- BN apply: out = g_t * sc + sh ----
    if (tid < 128) {
        float m = g_sum[1][tid] * invN;
        float var = g_sq[1][tid] * invN - m * m;
        float s = g2[tid] * rsqrtf(var + 1e-5f);
        s_sc[tid] = s;
        s_sh[tid] = be2[tid] - m * s;
    }
    __syncthreads();
    int stride = ncta * 512;
    for (int i = blockIdx.x * 512 + tid; i < n4; i += stride) {
        int c = (i & 31) * 4;
        float4 v = g_t4[i];
        float4 a = *(const float4*)&s_sc[c];
        float4 b = *(const float4*)&s_sh[c];
        v.x = fmaf(v.x, a.x, b.x); v.y = fmaf(v.y, a.y, b.y);
        v.z = fmaf(v.z, a.z, b.z); v.w = fmaf(v.w, a.w, b.w);
        dst[i] = v;
    }
}

// ===========================================================================
// Launch
// ===========================================================================
extern "C" void kernel_launch(void* const* d_in, const int* in_sizes, int n_in,
                              void* d_out, int out_size) {
    const float* x    = (const float*)d_in[0];
    const void*  eidx = d_in[1];
    const float* W1   = (const float*)d_in[2];
    const float* b1   = (const float*)d_in[3];
    const float* W2   = (const float*)d_in[4];
    const float* b2   = (const float*)d_in[5];
    const float* g1   = (const float*)d_in[6];
    const float* be1  = (const float*)d_in[7];
    const float* g2   = (const float*)d_in[8];
    const float* be2  = (const float*)d_in[9];

    int N = in_sizes[0] / 128;
    int E = in_sizes[1] / 2;
    int n4 = N * 32;
    int egrid = (E + 255) / 256;
    int nb = (N + 1 + SCAN_B - 1) / SCAN_B;     // <= 49 blocks (co-resident)
    int ntiles = (N + 63) / 64;
    int pgrid = 296;                            // 2 CTAs/SM x 148 SMs
    if (pgrid > ntiles) pgrid = ntiles;
    int xblk = (N * 64 + 255) / 256;
    float invN = 1.0f / (float)N;

    cudaFuncSetAttribute(fused_all_kernel,
                         cudaFuncAttributeMaxDynamicSharedMemorySize, GEMM_SMEM_TOTAL);

    prep_kernel<<<64 + xblk, 256>>>(W1, W2, x, (const int*)eidx, E, N);
    hist_kernel<<<egrid, 256>>>(eidx, E);
    scan_kernel<<<nb, SCAN_T>>>(N);
    fill_kernel<<<egrid, 256>>>(eidx, E);
    fused_all_kernel<<<pgrid, 512, GEMM_SMEM_TOTAL>>>(
        b1, b2, g1, be1, g2, be2, (float4*)d_out, invN, N, ntiles, n4);
}

// round 15
// speedup vs baseline: 1.0424x; 1.0424x over previous
#include <cuda_runtime.h>
#include <cuda_fp16.h>
#include <cstdint>

typedef unsigned long long u64;
typedef uint32_t u32;

#define MAXN 50176
#define MAXE 800000

__device__ u32 g_x16[(size_t)MAXN * 64];      // x as fp16 pairs; reused for h2 pre-BN
__device__ u32 g_h16[(size_t)MAXN * 64];      // h1 as fp16 pairs [N][64]
__device__ __align__(16) float g_sum[2][128];
__device__ __align__(16) float g_sq[2][128];
__device__ int g_idx64;
__device__ int g_cnt[MAXN];
__device__ int g_rowptr[MAXN + 1];
__device__ int g_cursor[MAXN];
__device__ int g_adj[MAXE];
// decoupled-lookback scan state (re-zeroed each launch by prep)
__device__ volatile int g_sstat[64];
__device__ volatile int g_sagg[64];
__device__ volatile int g_sinc[64];
// W fragments (mma B-operand layout), fp16 pairs, per layer.
__device__ __align__(16) u32 g_wf[2][8192];

// ===========================================================================
// Edge index accessors
// ===========================================================================
__device__ __forceinline__ int edge_src(const void* eidx, int E, int e) {
    if (g_idx64) return (int)((const long long*)eidx)[e];
    return ((const int*)eidx)[e];
}
__device__ __forceinline__ int edge_dst(const void* eidx, int E, int e) {
    if (g_idx64) return (int)((const long long*)eidx)[(size_t)E + e];
    return ((const int*)eidx)[E + e];
}

// ===========================================================================
// K1: combined init + prep.
// ===========================================================================
__global__ void __launch_bounds__(256) prep_kernel(const float* __restrict__ W1,
                                                   const float* __restrict__ W2,
                                                   const float* __restrict__ x,
                                                   const int* __restrict__ w,
                                                   int E, int N) {
    int b = blockIdx.x, t = threadIdx.x;
    if (b < 64) {
        int i = b * 256 + t;            // 0..16383
        int l = i >> 13;
        int j = i & 8191;
        int n = j & 127;                // coalesced over n
        int k = (j >> 7) * 2;
        const float* W = l ? W2 : W1;
        float v0 = W[k * 128 + n];
        float v1 = W[(k + 1) * 128 + n];
        __half2 p = __float22half2_rn(make_float2(v0, v1));
        int idx = ((((n >> 3) * 8) + (k >> 4)) * 32 + (n & 7) * 4 + ((k & 7) >> 1)) * 2
                  + ((k >> 3) & 1);
        g_wf[l][idx] = *(u32*)&p;
        return;
    }
    int j = (b - 64) * 256 + t;         // u32 output index over N*64
    if (j < N * 64) {
        float2 v = *(const float2*)(x + (size_t)j * 2);
        __half2 p = __float22half2_rn(v);
        g_x16[j] = *(u32*)&p;
    }
    if (j < N) g_cnt[j] = 0;
    if (b == 64) {
        __shared__ int any;
        if (t == 0) any = 0;
        __syncthreads();
        int limit = 2 * E; if (limit > 8192) limit = 8192;
        for (int q = 1 + 2 * t; q < limit; q += 512)
            if (w[q] != 0) any = 1;
        __syncthreads();
        if (t == 0) g_idx64 = (any == 0) ? 1 : 0;
        if (t < 128) {
            g_sum[0][t] = 0.f; g_sum[1][t] = 0.f;
            g_sq[0][t]  = 0.f; g_sq[1][t]  = 0.f;
        }
        if (t < 64) { g_sstat[t] = 0; g_sagg[t] = 0; g_sinc[t] = 0; }
    }
}

// ===========================================================================
// K2: histogram of dst.
// ===========================================================================
__global__ void __launch_bounds__(256) hist_kernel(const void* __restrict__ eidx, int E) {
    int e = blockIdx.x * 256 + threadIdx.x;
    if (e < E) atomicAdd(&g_cnt[edge_dst(eidx, E, e)], 1);
}

// ===========================================================================
// K3: single-pass exclusive scan (decoupled lookback) -> rowptr + cursor.
// ===========================================================================
#define SCAN_T 256
#define SCAN_E 4
#define SCAN_B (SCAN_T * SCAN_E)

__global__ void __launch_bounds__(SCAN_T) scan_kernel(int N) {
    __shared__ int sh[SCAN_T];
    __shared__ int s_prefix;
    int b = blockIdx.x, t = threadIdx.x;
    int base = b * SCAN_B + t * SCAN_E;
    int v[SCAN_E];
    int s = 0;
#pragma unroll
    for (int i = 0; i < SCAN_E; i++) {
        v[i] = (base + i < N) ? g_cnt[base + i] : 0;
        s += v[i];
    }
    sh[t] = s;
    __syncthreads();
    for (int off = 1; off < SCAN_T; off <<= 1) {
        int u = 0;
        if (t >= off) u = sh[t - off];
        __syncthreads();
        if (t >= off) sh[t] += u;
        __syncthreads();
    }
    int total = sh[SCAN_T - 1];
    int lrun = (t == 0) ? 0 : sh[t - 1];

    if (t == 0) {
        if (b == 0) {
            g_sinc[0] = total;
            __threadfence();
            g_sstat[0] = 2;
            s_prefix = 0;
        } else {
            g_sagg[b] = total;
            __threadfence();
            g_sstat[b] = 1;
            int prefix = 0;
            int idx = b - 1;
            while (true) {
                int st = g_sstat[idx];
                if (st == 2) { prefix += g_sinc[idx]; break; }
                if (st == 1) { prefix += g_sagg[idx]; idx--; }
            }
            g_sinc[b] = prefix + total;
            __threadfence();
            g_sstat[b] = 2;
            s_prefix = prefix;
        }
    }
    __syncthreads();
    int run = s_prefix + lrun;
#pragma unroll
    for (int i = 0; i < SCAN_E; i++) {
        if (base + i <= N) {
            g_rowptr[base + i] = run;
            if (base + i < N) g_cursor[base + i] = run;
        }
        run += v[i];
    }
}

// ===========================================================================
// K4: CSR fill.
// ===========================================================================
__global__ void __launch_bounds__(256) fill_kernel(const void* __restrict__ eidx, int E) {
    int e = blockIdx.x * 256 + threadIdx.x;
    if (e >= E) return;
    int d = edge_dst(eidx, E, e);
    int s = edge_src(eidx, E, e);
    int pos = atomicAdd(&g_cursor[d], 1);
    g_adj[pos] = s;
}

// ===========================================================================
// A fragment slot for row r (0..63), even col k (0..126)
// ===========================================================================
__device__ __forceinline__ int a_fragidx(int r, int k) {
    return (((r >> 4) * 8 + (k >> 4)) * 32 + (r & 7) * 4 + ((k & 7) >> 1)) * 4
           + ((k >> 3) & 1) * 2 + ((r >> 3) & 1);
}

// ===========================================================================
// K5/K6: fused persistent layer (single fp16): CSR gather -> fp16 fragments
// -> mma.sync f16 -> bias + ReLU -> fp16 out + stats (on quantized values).
// LAYER 0: in g_x16 -> out g_h16.  LAYER 1: in g_h16 -> out g_x16 (x dead).
// 64-row tiles, 512 threads, 2 CTAs/SM, persistent (B + sc/sh loaded once).
// ===========================================================================
#define SM_SSUM 0
#define SM_SSQ  512
#define SM_SC   1024
#define SM_SH   1536
#define SM_A    2048
#define SM_B    (2048 + 16384)
#define GEMM_SMEM_TOTAL (2048 + 16384 + 32768)

__device__ __forceinline__ void mma_f16(float* c, const u32* a, const u32* b) {
    asm volatile(
        "mma.sync.aligned.m16n8k16.row.col.f32.f16.f16.f32 "
        "{%0,%1,%2,%3}, {%4,%5,%6,%7}, {%8,%9}, {%0,%1,%2,%3};"
        : "+f"(c[0]), "+f"(c[1]), "+f"(c[2]), "+f"(c[3])
        : "r"(a[0]), "r"(a[1]), "r"(a[2]), "r"(a[3]), "r"(b[0]), "r"(b[1]));
}

__device__ __forceinline__ void acc_u2(float4& acc, uint2 u) {
    float2 f0 = __half22float2(*(__half2*)&u.x);
    float2 f1 = __half22float2(*(__half2*)&u.y);
    acc.x += f0.x; acc.y += f0.y; acc.z += f1.x; acc.w += f1.y;
}

template <int LAYER>
__global__ void __launch_bounds__(512, 2) fused_layer_kernel(
        const float* __restrict__ bias,
        const float* __restrict__ gamma0,  // LAYER==1: BN params of layer 0
        const float* __restrict__ beta0,
        float invN, int N, int ntiles) {
    extern __shared__ char smem[];
    float* s_sum = (float*)(smem + SM_SSUM);
    float* s_sq  = (float*)(smem + SM_SSQ);
    float* s_sc  = (float*)(smem + SM_SC);
    float* s_sh  = (float*)(smem + SM_SH);
    u32* AF = (u32*)(smem + SM_A);
    u32* BF = (u32*)(smem + SM_B);

    int tid = threadIdx.x, wid = tid >> 5, lane = tid & 31;
    const u32* base = LAYER ? g_h16 : g_x16;
    u32* outbuf     = LAYER ? g_x16 : g_h16;

    // ---- One-time: B fragments + (layer1) sc/sh ----
    if (LAYER == 1 && tid < 128) {
        float m = g_sum[0][tid] * invN;
        float var = g_sq[0][tid] * invN - m * m;
        float s = gamma0[tid] * rsqrtf(var + 1e-5f);
        s_sc[tid] = s;
        s_sh[tid] = beta0[tid] - m * s;
    }
    {
        const float4* sf = (const float4*)g_wf[LAYER];
        float4* df = (float4*)BF;
        for (int p = tid; p < 2048; p += 512) df[p] = sf[p];
    }
    __syncthreads();

    float4 sc4, sh4;
    if (LAYER == 1) {
        sc4 = *(const float4*)&s_sc[lane * 4];
        sh4 = *(const float4*)&s_sh[lane * 4];
    }

    int wm = wid & 3, wn = wid >> 2;
    int g = lane >> 2, tig = lane & 3;

    for (int tile = blockIdx.x; tile < ntiles; tile += gridDim.x) {
        int row0 = tile * 64;

        if (tid < 128) { s_sum[tid] = 0.f; s_sq[tid] = 0.f; }

        // ---- Gather + fragment conversion: warp handles 4 rows ----
#pragma unroll 1
        for (int ni = 0; ni < 4; ni++) {
            int r = wid * 4 + ni;
            int gr = row0 + r;
            float4 acc = make_float4(0.f, 0.f, 0.f, 0.f);
            float cnt = 0.f;
            if (gr < N) {
                acc_u2(acc, *(const uint2*)(base + (size_t)gr * 64 + lane * 2));
                int start = g_rowptr[gr];
                int end   = g_rowptr[gr + 1];
                cnt = (float)(end - start + 1);
                for (int j0 = start; j0 < end; j0 += 32) {
                    int n = end - j0; if (n > 32) n = 32;
                    int myIdx = (lane < n) ? g_adj[j0 + lane] : 0;
                    int k = 0;
                    for (; k + 8 <= n; k += 8) {
                        uint2 u[8];
#pragma unroll
                        for (int q = 0; q < 8; q++) {
                            int nb = __shfl_sync(0xffffffffu, myIdx, k + q);
                            u[q] = *(const uint2*)(base + (size_t)nb * 64 + lane * 2);
                        }
#pragma unroll
                        for (int q = 0; q < 8; q++) acc_u2(acc, u[q]);
                    }
                    for (; k < n; k++) {
                        int nb = __shfl_sync(0xffffffffu, myIdx, k);
                        acc_u2(acc, *(const uint2*)(base + (size_t)nb * 64 + lane * 2));
                    }
                }
            }
            float4 tv;
            if (LAYER == 1) {
                tv.x = fmaf(acc.x, sc4.x, cnt * sh4.x);
                tv.y = fmaf(acc.y, sc4.y, cnt * sh4.y);
                tv.z = fmaf(acc.z, sc4.z, cnt * sh4.z);
                tv.w = fmaf(acc.w, sc4.w, cnt * sh4.w);
            } else {
                tv = acc;
            }
            __half2 p0 = __float22half2_rn(make_float2(tv.x, tv.y));
            __half2 p1 = __float22half2_rn(make_float2(tv.z, tv.w));
            int k0 = lane * 4;
            AF[a_fragidx(r, k0)]     = *(u32*)&p0;
            AF[a_fragidx(r, k0 + 2)] = *(u32*)&p1;
        }
        __syncthreads();

        // ---- MMA: warp tile 16 rows (wm) x 32 cols (wn quarter) ----
        float acc[4][4];
#pragma unroll
        for (int n = 0; n < 4; n++)
#pragma unroll
            for (int q = 0; q < 4; q++) acc[n][q] = 0.f;

#pragma unroll
        for (int kt = 0; kt < 8; kt++) {
            u32 ah[4];
            {
                int bq = ((wm * 8 + kt) * 32 + lane) * 4;
                *(uint4*)ah = *(const uint4*)(AF + bq);
            }
#pragma unroll
            for (int n = 0; n < 4; n++) {
                u32 bf[2];
                int bq = (((wn * 4 + n) * 8 + kt) * 32 + lane) * 2;
                *(uint2*)bf = *(const uint2*)(BF + bq);
                mma_f16(acc[n], ah, bf);
            }
        }

        // ---- Epilogue: bias + relu -> fp16 store + stats on quantized ----
#pragma unroll
        for (int n = 0; n < 4; n++) {
            int cbase = wn * 32 + n * 8 + tig * 2;
            float2 bb = *(const float2*)(bias + cbase);
            float s0 = 0.f, s1 = 0.f, q0 = 0.f, q1 = 0.f;
            int rb = row0 + wm * 16 + g;
#pragma unroll
            for (int rh = 0; rh < 2; rh++) {
                int gr = rb + rh * 8;
                float h0 = fmaxf(acc[n][rh * 2 + 0] + bb.x, 0.f);
                float h1 = fmaxf(acc[n][rh * 2 + 1] + bb.y, 0.f);
                if (gr < N) {
                    __half2 hq = __float22half2_rn(make_float2(h0, h1));
                    outbuf[(size_t)gr * 64 + (cbase >> 1)] = *(u32*)&hq;
                    float2 hf = __half22float2(hq);
                    h0 = hf.x; h1 = hf.y;   // stats on quantized values
                    s0 += h0; s1 += h1;
                    q0 += h0 * h0; q1 += h1 * h1;
                }
            }
#pragma unroll
            for (int o = 4; o < 32; o <<= 1) {
                s0 += __shfl_xor_sync(0xffffffffu, s0, o);
                s1 += __shfl_xor_sync(0xffffffffu, s1, o);
                q0 += __shfl_xor_sync(0xffffffffu, q0, o);
                q1 += __shfl_xor_sync(0xffffffffu, q1, o);
            }
            if (g == 0) {
                atomicAdd(&s_sum[cbase], s0);
                atomicAdd(&s_sum[cbase + 1], s1);
                atomicAdd(&s_sq[cbase], q0);
                atomicAdd(&s_sq[cbase + 1], q1);
            }
        }

        __syncthreads();
        if (tid < 128) {
            atomicAdd(&g_sum[LAYER][tid], s_sum[tid]);
            atomicAdd(&g_sq[LAYER][tid], s_sq[tid]);
        }
        __syncthreads();   // stats consumed before next tile re-zeroes
    }
}

// ===========================================================================
// K7: final BN apply: out = fp16(h2) * sc + sh (reads g_x16, fp32 out).
// ===========================================================================
__global__ void __launch_bounds__(256) bn_apply_kernel(float2* __restrict__ dst,
                                                       const float* __restrict__ gamma,
                                                       const float* __restrict__ beta,
                                                       float invN, int n64) {
    __shared__ float s_sc[128], s_sh[128];
    if (threadIdx.x < 128) {
        int c = threadIdx.x;
        float m = g_sum[1][c] * invN;
        float var = g_sq[1][c] * invN - m * m;
        float s = gamma[c] * rsqrtf(var + 1e-5f);
        s_sc[c] = s;
        s_sh[c] = beta[c] - m * s;
    }
    __syncthreads();
    int i = blockIdx.x * 256 + threadIdx.x;
    if (i >= n64) return;
    int c = (i & 63) * 2;
    u32 u = g_x16[i];
    float2 v = __half22float2(*(__half2*)&u);
    float2 o;
    o.x = fmaf(v.x, s_sc[c],     s_sh[c]);
    o.y = fmaf(v.y, s_sc[c + 1], s_sh[c + 1]);
    dst[i] = o;
}

// ===========================================================================
// Launch
// ===========================================================================
extern "C" void kernel_launch(void* const* d_in, const int* in_sizes, int n_in,
                              void* d_out, int out_size) {
    const float* x    = (const float*)d_in[0];
    const void*  eidx = d_in[1];
    const float* W1   = (const float*)d_in[2];
    const float* b1   = (const float*)d_in[3];
    const float* W2   = (const float*)d_in[4];
    const float* b2   = (const float*)d_in[5];
    const float* g1   = (const float*)d_in[6];
    const float* be1  = (const float*)d_in[7];
    const float* g2   = (const float*)d_in[8];
    const float* be2  = (const float*)d_in[9];

    int N = in_sizes[0] / 128;
    int E = in_sizes[1] / 2;
    int n64 = N * 64;
    int agrid = (n64 + 255) / 256;
    int egrid = (E + 255) / 256;
    int nb = (N + 1 + SCAN_B - 1) / SCAN_B;     // <= 49 blocks (co-resident)
    int ntiles = (N + 63) / 64;
    int pgrid = 296;                            // 2 CTAs/SM x 148 SMs
    if (pgrid > ntiles) pgrid = ntiles;
    int xblk = (n64 + 255) / 256;
    float invN = 1.0f / (float)N;

    cudaFuncSetAttribute(fused_layer_kernel<0>,
                         cudaFuncAttributeMaxDynamicSharedMemorySize, GEMM_SMEM_TOTAL);
    cudaFuncSetAttribute(fused_layer_kernel<1>,
                         cudaFuncAttributeMaxDynamicSharedMemorySize, GEMM_SMEM_TOTAL);

    // ---- CSR build + prep ----
    prep_kernel<<<64 + xblk, 256>>>(W1, W2, x, (const int*)eidx, E, N);
    hist_kernel<<<egrid, 256>>>(eidx, E);
    scan_kernel<<<nb, SCAN_T>>>(N);
    fill_kernel<<<egrid, 256>>>(eidx, E);

    // ---- Layer 1: gather(g_x16) + GEMM + stats -> g_h16 ----
    fused_layer_kernel<0><<<pgrid, 512, GEMM_SMEM_TOTAL>>>(b1, nullptr, nullptr, invN, N, ntiles);
    // ---- Layer 2: BN0-folded gather(g_h16) + GEMM + stats -> g_x16 ----
    fused_layer_kernel<1><<<pgrid, 512, GEMM_SMEM_TOTAL>>>(b2, g1, be1, invN, N, ntiles);
    // ---- Final BN apply -> d_out ----
    bn_apply_kernel<<<agrid, 256>>>((float2*)d_out, g2, be2, invN, n64);
}

// round 16
// speedup vs baseline: 1.0602x; 1.0170x over previous
#include <cuda_runtime.h>
#include <cuda_fp16.h>
#include <cstdint>

typedef unsigned long long u64;
typedef uint32_t u32;

#define MAXN 50176
#define MAXE 800000

__device__ u32 g_x16[(size_t)MAXN * 64];      // x as fp16 pairs; reused for h2 pre-BN
__device__ u32 g_h16[(size_t)MAXN * 64];      // h1 as fp16 pairs [N][64]
__device__ __align__(16) float g_sum[2][128];
__device__ __align__(16) float g_sq[2][128];
__device__ int g_idx64;
__device__ int g_cnt[MAXN];
__device__ int g_rowptr[MAXN + 1];
__device__ int g_cursor[MAXN];
__device__ int g_adj[MAXE];
// decoupled-lookback scan state (re-zeroed each launch by prep)
__device__ volatile int g_sstat[64];
__device__ volatile int g_sagg[64];
__device__ volatile int g_sinc[64];
// W fragments (mma B-operand layout), fp16 pairs, per layer.
__device__ __align__(16) u32 g_wf[2][8192];

// ===========================================================================
// Edge index accessors
// ===========================================================================
__device__ __forceinline__ int edge_src(const void* eidx, int E, int e) {
    if (g_idx64) return (int)((const long long*)eidx)[e];
    return ((const int*)eidx)[e];
}
__device__ __forceinline__ int edge_dst(const void* eidx, int E, int e) {
    if (g_idx64) return (int)((const long long*)eidx)[(size_t)E + e];
    return ((const int*)eidx)[E + e];
}

// ===========================================================================
// K1: combined init + prep.
// ===========================================================================
__global__ void __launch_bounds__(256) prep_kernel(const float* __restrict__ W1,
                                                   const float* __restrict__ W2,
                                                   const float* __restrict__ x,
                                                   const int* __restrict__ w,
                                                   int E, int N) {
    int b = blockIdx.x, t = threadIdx.x;
    if (b < 64) {
        int i = b * 256 + t;            // 0..16383
        int l = i >> 13;
        int j = i & 8191;
        int n = j & 127;                // coalesced over n
        int k = (j >> 7) * 2;
        const float* W = l ? W2 : W1;
        float v0 = W[k * 128 + n];
        float v1 = W[(k + 1) * 128 + n];
        __half2 p = __float22half2_rn(make_float2(v0, v1));
        int idx = ((((n >> 3) * 8) + (k >> 4)) * 32 + (n & 7) * 4 + ((k & 7) >> 1)) * 2
                  + ((k >> 3) & 1);
        g_wf[l][idx] = *(u32*)&p;
        return;
    }
    int j = (b - 64) * 256 + t;         // u32 output index over N*64
    if (j < N * 64) {
        float2 v = *(const float2*)(x + (size_t)j * 2);
        __half2 p = __float22half2_rn(v);
        g_x16[j] = *(u32*)&p;
    }
    if (j < N) g_cnt[j] = 0;
    if (b == 64) {
        __shared__ int any;
        if (t == 0) any = 0;
        __syncthreads();
        int limit = 2 * E; if (limit > 8192) limit = 8192;
        for (int q = 1 + 2 * t; q < limit; q += 512)
            if (w[q] != 0) any = 1;
        __syncthreads();
        if (t == 0) g_idx64 = (any == 0) ? 1 : 0;
        if (t < 128) {
            g_sum[0][t] = 0.f; g_sum[1][t] = 0.f;
            g_sq[0][t]  = 0.f; g_sq[1][t]  = 0.f;
        }
        if (t < 64) { g_sstat[t] = 0; g_sagg[t] = 0; g_sinc[t] = 0; }
    }
}

// ===========================================================================
// K2: histogram of dst (4 edges per thread, batched loads).
// ===========================================================================
__global__ void __launch_bounds__(256) hist_kernel(const void* __restrict__ eidx, int E) {
    int base = blockIdx.x * 1024 + threadIdx.x;
    int d[4];
#pragma unroll
    for (int q = 0; q < 4; q++) {
        int e = base + q * 256;
        d[q] = (e < E) ? edge_dst(eidx, E, e) : -1;
    }
#pragma unroll
    for (int q = 0; q < 4; q++)
        if (d[q] >= 0) atomicAdd(&g_cnt[d[q]], 1);
}

// ===========================================================================
// K3: single-pass exclusive scan (decoupled lookback) -> rowptr + cursor.
// ===========================================================================
#define SCAN_T 256
#define SCAN_E 4
#define SCAN_B (SCAN_T * SCAN_E)

__global__ void __launch_bounds__(SCAN_T) scan_kernel(int N) {
    __shared__ int sh[SCAN_T];
    __shared__ int s_prefix;
    int b = blockIdx.x, t = threadIdx.x;
    int base = b * SCAN_B + t * SCAN_E;
    int v[SCAN_E];
    int s = 0;
#pragma unroll
    for (int i = 0; i < SCAN_E; i++) {
        v[i] = (base + i < N) ? g_cnt[base + i] : 0;
        s += v[i];
    }
    sh[t] = s;
    __syncthreads();
    for (int off = 1; off < SCAN_T; off <<= 1) {
        int u = 0;
        if (t >= off) u = sh[t - off];
        __syncthreads();
        if (t >= off) sh[t] += u;
        __syncthreads();
    }
    int total = sh[SCAN_T - 1];
    int lrun = (t == 0) ? 0 : sh[t - 1];

    if (t == 0) {
        if (b == 0) {
            g_sinc[0] = total;
            __threadfence();
            g_sstat[0] = 2;
            s_prefix = 0;
        } else {
            g_sagg[b] = total;
            __threadfence();
            g_sstat[b] = 1;
            int prefix = 0;
            int idx = b - 1;
            while (true) {
                int st = g_sstat[idx];
                if (st == 2) { prefix += g_sinc[idx]; break; }
                if (st == 1) { prefix += g_sagg[idx]; idx--; }
            }
            g_sinc[b] = prefix + total;
            __threadfence();
            g_sstat[b] = 2;
            s_prefix = prefix;
        }
    }
    __syncthreads();
    int run = s_prefix + lrun;
#pragma unroll
    for (int i = 0; i < SCAN_E; i++) {
        if (base + i <= N) {
            g_rowptr[base + i] = run;
            if (base + i < N) g_cursor[base + i] = run;
        }
        run += v[i];
    }
}

// ===========================================================================
// K4: CSR fill (4 edges per thread, batched loads).
// ===========================================================================
__global__ void __launch_bounds__(256) fill_kernel(const void* __restrict__ eidx, int E) {
    int base = blockIdx.x * 1024 + threadIdx.x;
    int d[4], s[4];
#pragma unroll
    for (int q = 0; q < 4; q++) {
        int e = base + q * 256;
        if (e < E) { d[q] = edge_dst(eidx, E, e); s[q] = edge_src(eidx, E, e); }
        else d[q] = -1;
    }
#pragma unroll
    for (int q = 0; q < 4; q++) {
        if (d[q] >= 0) {
            int pos = atomicAdd(&g_cursor[d[q]], 1);
            g_adj[pos] = s[q];
        }
    }
}

// ===========================================================================
// A fragment slot for row r (0..63), even col k (0..126)
// ===========================================================================
__device__ __forceinline__ int a_fragidx(int r, int k) {
    return (((r >> 4) * 8 + (k >> 4)) * 32 + (r & 7) * 4 + ((k & 7) >> 1)) * 4
           + ((k >> 3) & 1) * 2 + ((r >> 3) & 1);
}

// ===========================================================================
// K5/K6: fused persistent layer with per-group pipelines.
// 16 warps = 4 groups of 4 (group = wm = wid&3). Group wm owns A rows
// [wm*16, wm*16+16): each of its 4 warps (wn = wid>>2) gathers 4 rows, then
// bar.sync(1+wm,128), then MMA of mtile wm x cols wn*32. Groups never wait
// on each other (degree-variance hiding). Stats in smem, flushed once.
// LAYER 0: in g_x16 -> out g_h16.  LAYER 1: in g_h16 -> out g_x16.
// ===========================================================================
#define SM_SSUM 0
#define SM_SSQ  512
#define SM_SC   1024
#define SM_SH   1536
#define SM_A    2048
#define SM_B    (2048 + 16384)
#define GEMM_SMEM_TOTAL (2048 + 16384 + 32768)

__device__ __forceinline__ void mma_f16(float* c, const u32* a, const u32* b) {
    asm volatile(
        "mma.sync.aligned.m16n8k16.row.col.f32.f16.f16.f32 "
        "{%0,%1,%2,%3}, {%4,%5,%6,%7}, {%8,%9}, {%0,%1,%2,%3};"
        : "+f"(c[0]), "+f"(c[1]), "+f"(c[2]), "+f"(c[3])
        : "r"(a[0]), "r"(a[1]), "r"(a[2]), "r"(a[3]), "r"(b[0]), "r"(b[1]));
}

__device__ __forceinline__ void acc_u2(float4& acc, uint2 u) {
    float2 f0 = __half22float2(*(__half2*)&u.x);
    float2 f1 = __half22float2(*(__half2*)&u.y);
    acc.x += f0.x; acc.y += f0.y; acc.z += f1.x; acc.w += f1.y;
}

#define GROUP_BAR(id) asm volatile("bar.sync %0, 128;" :: "r"(id) : "memory")

template <int LAYER>
__global__ void __launch_bounds__(512, 2) fused_layer_kernel(
        const float* __restrict__ bias,
        const float* __restrict__ gamma0,  // LAYER==1: BN params of layer 0
        const float* __restrict__ beta0,
        float invN, int N, int ntiles) {
    extern __shared__ char smem[];
    float* s_sum = (float*)(smem + SM_SSUM);
    float* s_sq  = (float*)(smem + SM_SSQ);
    float* s_sc  = (float*)(smem + SM_SC);
    float* s_sh  = (float*)(smem + SM_SH);
    u32* AF = (u32*)(smem + SM_A);
    u32* BF = (u32*)(smem + SM_B);

    int tid = threadIdx.x, wid = tid >> 5, lane = tid & 31;
    const u32* base = LAYER ? g_h16 : g_x16;
    u32* outbuf     = LAYER ? g_x16 : g_h16;

    // ---- One-time: B fragments + (layer1) sc/sh + zero stats ----
    if (tid < 128) {
        s_sum[tid] = 0.f; s_sq[tid] = 0.f;
        if (LAYER == 1) {
            float m = g_sum[0][tid] * invN;
            float var = g_sq[0][tid] * invN - m * m;
            float s = gamma0[tid] * rsqrtf(var + 1e-5f);
            s_sc[tid] = s;
            s_sh[tid] = beta0[tid] - m * s;
        }
    }
    {
        const float4* sf = (const float4*)g_wf[LAYER];
        float4* df = (float4*)BF;
        for (int p = tid; p < 2048; p += 512) df[p] = sf[p];
    }
    __syncthreads();

    float4 sc4, sh4;
    if (LAYER == 1) {
        sc4 = *(const float4*)&s_sc[lane * 4];
        sh4 = *(const float4*)&s_sh[lane * 4];
    }

    int wm = wid & 3, wn = wid >> 2;
    int barid = 1 + wm;
    int g = lane >> 2, tig = lane & 3;

    for (int tile = blockIdx.x; tile < ntiles; tile += gridDim.x) {
        int row0 = tile * 64;

        // ---- Gather: warp (wm,wn) gathers rows wm*16 + wn*4 + ni ----
#pragma unroll 1
        for (int ni = 0; ni < 4; ni++) {
            int r = wm * 16 + wn * 4 + ni;
            int gr = row0 + r;
            float4 acc = make_float4(0.f, 0.f, 0.f, 0.f);
            float cnt = 0.f;
            if (gr < N) {
                acc_u2(acc, *(const uint2*)(base + (size_t)gr * 64 + lane * 2));
                int start = g_rowptr[gr];
                int end   = g_rowptr[gr + 1];
                cnt = (float)(end - start + 1);
                for (int j0 = start; j0 < end; j0 += 32) {
                    int n = end - j0; if (n > 32) n = 32;
                    int myIdx = (lane < n) ? g_adj[j0 + lane] : 0;
                    int k = 0;
                    for (; k + 8 <= n; k += 8) {
                        uint2 u[8];
#pragma unroll
                        for (int q = 0; q < 8; q++) {
                            int nb = __shfl_sync(0xffffffffu, myIdx, k + q);
                            u[q] = *(const uint2*)(base + (size_t)nb * 64 + lane * 2);
                        }
#pragma unroll
                        for (int q = 0; q < 8; q++) acc_u2(acc, u[q]);
                    }
                    for (; k < n; k++) {
                        int nb = __shfl_sync(0xffffffffu, myIdx, k);
                        acc_u2(acc, *(const uint2*)(base + (size_t)nb * 64 + lane * 2));
                    }
                }
            }
            float4 tv;
            if (LAYER == 1) {
                tv.x = fmaf(acc.x, sc4.x, cnt * sh4.x);
                tv.y = fmaf(acc.y, sc4.y, cnt * sh4.y);
                tv.z = fmaf(acc.z, sc4.z, cnt * sh4.z);
                tv.w = fmaf(acc.w, sc4.w, cnt * sh4.w);
            } else {
                tv = acc;
            }
            __half2 p0 = __float22half2_rn(make_float2(tv.x, tv.y));
            __half2 p1 = __float22half2_rn(make_float2(tv.z, tv.w));
            int k0 = lane * 4;
            AF[a_fragidx(r, k0)]     = *(u32*)&p0;
            AF[a_fragidx(r, k0 + 2)] = *(u32*)&p1;
        }
        GROUP_BAR(barid);    // group's 16 A rows ready

        // ---- MMA: warp tile 16 rows (wm) x 32 cols (wn quarter) ----
        float acc[4][4];
#pragma unroll
        for (int n = 0; n < 4; n++)
#pragma unroll
            for (int q = 0; q < 4; q++) acc[n][q] = 0.f;

#pragma unroll
        for (int kt = 0; kt < 8; kt++) {
            u32 ah[4];
            {
                int bq = ((wm * 8 + kt) * 32 + lane) * 4;
                *(uint4*)ah = *(const uint4*)(AF + bq);
            }
#pragma unroll
            for (int n = 0; n < 4; n++) {
                u32 bf[2];
                int bq = (((wn * 4 + n) * 8 + kt) * 32 + lane) * 2;
                *(uint2*)bf = *(const uint2*)(BF + bq);
                mma_f16(acc[n], ah, bf);
            }
        }

        // ---- Epilogue: bias + relu -> fp16 store + stats on quantized ----
#pragma unroll
        for (int n = 0; n < 4; n++) {
            int cbase = wn * 32 + n * 8 + tig * 2;
            float2 bb = *(const float2*)(bias + cbase);
            float s0 = 0.f, s1 = 0.f, q0 = 0.f, q1 = 0.f;
            int rb = row0 + wm * 16 + g;
#pragma unroll
            for (int rh = 0; rh < 2; rh++) {
                int gr = rb + rh * 8;
                float h0 = fmaxf(acc[n][rh * 2 + 0] + bb.x, 0.f);
                float h1 = fmaxf(acc[n][rh * 2 + 1] + bb.y, 0.f);
                if (gr < N) {
                    __half2 hq = __float22half2_rn(make_float2(h0, h1));
                    outbuf[(size_t)gr * 64 + (cbase >> 1)] = *(u32*)&hq;
                    float2 hf = __half22float2(hq);
                    h0 = hf.x; h1 = hf.y;   // stats on quantized values
                    s0 += h0; s1 += h1;
                    q0 += h0 * h0; q1 += h1 * h1;
                }
            }
#pragma unroll
            for (int o = 4; o < 32; o <<= 1) {
                s0 += __shfl_xor_sync(0xffffffffu, s0, o);
                s1 += __shfl_xor_sync(0xffffffffu, s1, o);
                q0 += __shfl_xor_sync(0xffffffffu, q0, o);
                q1 += __shfl_xor_sync(0xffffffffu, q1, o);
            }
            if (g == 0) {
                atomicAdd(&s_sum[cbase], s0);
                atomicAdd(&s_sum[cbase + 1], s1);
                atomicAdd(&s_sq[cbase], q0);
                atomicAdd(&s_sq[cbase + 1], q1);
            }
        }
        GROUP_BAR(barid);    // AF reads done before next tile's gather writes
    }

    // ---- Flush stats once ----
    __syncthreads();
    if (tid < 128) {
        atomicAdd(&g_sum[LAYER][tid], s_sum[tid]);
        atomicAdd(&g_sq[LAYER][tid], s_sq[tid]);
    }
}

// ===========================================================================
// K7: final BN apply: out = fp16(h2) * sc + sh (reads g_x16, fp32 out).
// ===========================================================================
__global__ void __launch_bounds__(256) bn_apply_kernel(float2* __restrict__ dst,
                                                       const float* __restrict__ gamma,
                                                       const float* __restrict__ beta,
                                                       float invN, int n64) {
    __shared__ float s_sc[128], s_sh[128];
    if (threadIdx.x < 128) {
        int c = threadIdx.x;
        float m = g_sum[1][c] * invN;
        float var = g_sq[1][c] * invN - m * m;
        float s = gamma[c] * rsqrtf(var + 1e-5f);
        s_sc[c] = s;
        s_sh[c] = beta[c] - m * s;
    }
    __syncthreads();
    int i = blockIdx.x * 256 + threadIdx.x;
    if (i >= n64) return;
    int c = (i & 63) * 2;
    u32 u = g_x16[i];
    float2 v = __half22float2(*(__half2*)&u);
    float2 o;
    o.x = fmaf(v.x, s_sc[c],     s_sh[c]);
    o.y = fmaf(v.y, s_sc[c + 1], s_sh[c + 1]);
    dst[i] = o;
}

// ===========================================================================
// Launch
// ===========================================================================
extern "C" void kernel_launch(void* const* d_in, const int* in_sizes, int n_in,
                              void* d_out, int out_size) {
    const float* x    = (const float*)d_in[0];
    const void*  eidx = d_in[1];
    const float* W1   = (const float*)d_in[2];
    const float* b1   = (const float*)d_in[3];
    const float* W2   = (const float*)d_in[4];
    const float* b2   = (const float*)d_in[5];
    const float* g1   = (const float*)d_in[6];
    const float* be1  = (const float*)d_in[7];
    const float* g2   = (const float*)d_in[8];
    const float* be2  = (const float*)d_in[9];

    int N = in_sizes[0] / 128;
    int E = in_sizes[1] / 2;
    int n64 = N * 64;
    int agrid = (n64 + 255) / 256;
    int e4grid = (E + 1023) / 1024;
    int nb = (N + 1 + SCAN_B - 1) / SCAN_B;     // <= 49 blocks (co-resident)
    int ntiles = (N + 63) / 64;
    int pgrid = 296;                            // 2 CTAs/SM x 148 SMs
    if (pgrid > ntiles) pgrid = ntiles;
    int xblk = (n64 + 255) / 256;
    float invN = 1.0f / (float)N;

    cudaFuncSetAttribute(fused_layer_kernel<0>,
                         cudaFuncAttributeMaxDynamicSharedMemorySize, GEMM_SMEM_TOTAL);
    cudaFuncSetAttribute(fused_layer_kernel<1>,
                         cudaFuncAttributeMaxDynamicSharedMemorySize, GEMM_SMEM_TOTAL);

    // ---- CSR build + prep ----
    prep_kernel<<<64 + xblk, 256>>>(W1, W2, x, (const int*)eidx, E, N);
    hist_kernel<<<e4grid, 256>>>(eidx, E);
    scan_kernel<<<nb, SCAN_T>>>(N);
    fill_kernel<<<e4grid, 256>>>(eidx, E);

    // ---- Layer 1: gather(g_x16) + GEMM + stats -> g_h16 ----
    fused_layer_kernel<0><<<pgrid, 512, GEMM_SMEM_TOTAL>>>(b1, nullptr, nullptr, invN, N, ntiles);
    // ---- Layer 2: BN0-folded gather(g_h16) + GEMM + stats -> g_x16 ----
    fused_layer_kernel<1><<<pgrid, 512, GEMM_SMEM_TOTAL>>>(b2, g1, be1, invN, N, ntiles);
    // ---- Final BN apply -> d_out ----
    bn_apply_kernel<<<agrid, 256>>>((float2*)d_out, g2, be2, invN, n64);
}

// round 17
// speedup vs baseline: 1.0868x; 1.0251x over previous
#include <cuda_runtime.h>
#include <cuda_fp16.h>
#include <cstdint>

typedef unsigned long long u64;
typedef uint32_t u32;

#define MAXN 50176
#define MAXE 800000

__device__ u32 g_x16[(size_t)MAXN * 64];      // x as fp16 pairs; reused for h2 pre-BN
__device__ u32 g_h16[(size_t)MAXN * 64];      // h1 as fp16 pairs [N][64]
__device__ __align__(16) float g_sum[2][128];
__device__ __align__(16) float g_sq[2][128];
__device__ int g_idx64;
__device__ int g_cnt[MAXN];                   // INVARIANT: all-zero at launch entry
__device__ int g_rowptr[MAXN + 1];
__device__ int g_adj[MAXE];
__device__ u32 g_slotd[MAXE];                 // (dst<<9)|slot per edge
// decoupled-lookback scan state (re-zeroed each launch by prep)
__device__ volatile int g_sstat[64];
__device__ volatile int g_sagg[64];
__device__ volatile int g_sinc[64];
// W fragments (mma B-operand layout), fp16 pairs, per layer.
__device__ __align__(16) u32 g_wf[2][8192];

// ===========================================================================
// Edge index accessors (global flag variant, used after prep completes)
// ===========================================================================
__device__ __forceinline__ int edge_src(const void* eidx, int E, int e) {
    if (g_idx64) return (int)((const long long*)eidx)[e];
    return ((const int*)eidx)[e];
}

// ===========================================================================
// K1: combined init + prep + histogram.
// blocks [0,64):              W^T -> fp16 mma B-fragments
// blocks [64, 64+xblk):       x -> fp16 (block 64 also: globals init)
// blocks [64+xblk, +hblk):    histogram with slot capture (local dtype probe)
// Requires g_cnt == 0 at entry (zero-init at load; scan re-zeroes each run).
// ===========================================================================
__global__ void __launch_bounds__(256) prep_kernel(const float* __restrict__ W1,
                                                   const float* __restrict__ W2,
                                                   const float* __restrict__ x,
                                                   const int* __restrict__ w,
                                                   int E, int N, int xblk) {
    int b = blockIdx.x, t = threadIdx.x;
    if (b < 64) {
        int i = b * 256 + t;            // 0..16383
        int l = i >> 13;
        int j = i & 8191;
        int n = j & 127;                // coalesced over n
        int k = (j >> 7) * 2;
        const float* W = l ? W2 : W1;
        float v0 = W[k * 128 + n];
        float v1 = W[(k + 1) * 128 + n];
        __half2 p = __float22half2_rn(make_float2(v0, v1));
        int idx = ((((n >> 3) * 8) + (k >> 4)) * 32 + (n & 7) * 4 + ((k & 7) >> 1)) * 2
                  + ((k >> 3) & 1);
        g_wf[l][idx] = *(u32*)&p;
        return;
    }
    if (b < 64 + xblk) {
        int j = (b - 64) * 256 + t;     // u32 output index over N*64
        if (j < N * 64) {
            float2 v = *(const float2*)(x + (size_t)j * 2);
            __half2 p = __float22half2_rn(v);
            g_x16[j] = *(u32*)&p;
        }
        if (b == 64) {
            __shared__ int any;
            if (t == 0) any = 0;
            __syncthreads();
            int limit = 2 * E; if (limit > 8192) limit = 8192;
            for (int q = 1 + 2 * t; q < limit; q += 512)
                if (w[q] != 0) any = 1;
            __syncthreads();
            if (t == 0) g_idx64 = (any == 0) ? 1 : 0;
            if (t < 128) {
                g_sum[0][t] = 0.f; g_sum[1][t] = 0.f;
                g_sq[0][t]  = 0.f; g_sq[1][t]  = 0.f;
            }
            if (t < 64) { g_sstat[t] = 0; g_sagg[t] = 0; g_sinc[t] = 0; }
        }
        return;
    }
    // ---- Histogram blocks: local dtype probe, then slot-capturing atomics.
    __shared__ int s_any;
    if (t == 0) {
        int any = 0;
        int limit = 2 * E; if (limit > 64) limit = 64;
        for (int q = 1; q < limit; q += 2) any |= w[q];
        s_any = any;
    }
    __syncthreads();
    bool loc64 = (s_any == 0);
    int base = (b - 64 - xblk) * 1024 + t;
    int d[4];
#pragma unroll
    for (int q = 0; q < 4; q++) {
        int e = base + q * 256;
        if (e < E)
            d[q] = loc64 ? (int)((const long long*)w)[(size_t)E + e]
                         : ((const int*)w)[E + e];
        else d[q] = -1;
    }
#pragma unroll
    for (int q = 0; q < 4; q++) {
        if (d[q] >= 0) {
            int slot = atomicAdd(&g_cnt[d[q]], 1);
            g_slotd[base + q * 256] = ((u32)d[q] << 9) | (u32)slot;
        }
    }
}

// ===========================================================================
// K2: single-pass exclusive scan (decoupled lookback) -> rowptr.
// Also re-zeroes g_cnt (maintains the entry invariant for the next replay).
// ===========================================================================
#define SCAN_T 256
#define SCAN_E 4
#define SCAN_B (SCAN_T * SCAN_E)

__global__ void __launch_bounds__(SCAN_T) scan_kernel(int N) {
    __shared__ int sh[SCAN_T];
    __shared__ int s_prefix;
    int b = blockIdx.x, t = threadIdx.x;
    int base = b * SCAN_B + t * SCAN_E;
    int v[SCAN_E];
    int s = 0;
#pragma unroll
    for (int i = 0; i < SCAN_E; i++) {
        if (base + i < N) {
            v[i] = g_cnt[base + i];
            g_cnt[base + i] = 0;        // re-zero for next launch
        } else v[i] = 0;
        s += v[i];
    }
    sh[t] = s;
    __syncthreads();
    for (int off = 1; off < SCAN_T; off <<= 1) {
        int u = 0;
        if (t >= off) u = sh[t - off];
        __syncthreads();
        if (t >= off) sh[t] += u;
        __syncthreads();
    }
    int total = sh[SCAN_T - 1];
    int lrun = (t == 0) ? 0 : sh[t - 1];

    if (t == 0) {
        if (b == 0) {
            g_sinc[0] = total;
            __threadfence();
            g_sstat[0] = 2;
            s_prefix = 0;
        } else {
            g_sagg[b] = total;
            __threadfence();
            g_sstat[b] = 1;
            int prefix = 0;
            int idx = b - 1;
            while (true) {
                int st = g_sstat[idx];
                if (st == 2) { prefix += g_sinc[idx]; break; }
                if (st == 1) { prefix += g_sagg[idx]; idx--; }
            }
            g_sinc[b] = prefix + total;
            __threadfence();
            g_sstat[b] = 2;
            s_prefix = prefix;
        }
    }
    __syncthreads();
    int run = s_prefix + lrun;
#pragma unroll
    for (int i = 0; i < SCAN_E; i++) {
        if (base + i <= N) g_rowptr[base + i] = run;
        run += v[i];
    }
}

// ===========================================================================
// K3: CSR fill, atomic-free: g_adj[rowptr[d] + slot] = src.
// ===========================================================================
__global__ void __launch_bounds__(256) fill_kernel(const void* __restrict__ eidx, int E) {
    int base = blockIdx.x * 1024 + threadIdx.x;
    int s[4], pos[4];
#pragma unroll
    for (int q = 0; q < 4; q++) {
        int e = base + q * 256;
        if (e < E) {
            u32 sd = g_slotd[e];
            int d = (int)(sd >> 9);
            int slot = (int)(sd & 511u);
            pos[q] = g_rowptr[d] + slot;
            s[q] = edge_src(eidx, E, e);
        } else pos[q] = -1;
    }
#pragma unroll
    for (int q = 0; q < 4; q++)
        if (pos[q] >= 0) g_adj[pos[q]] = s[q];
}

// ===========================================================================
// A fragment slot for row r (0..63), even col k (0..126)
// ===========================================================================
__device__ __forceinline__ int a_fragidx(int r, int k) {
    return (((r >> 4) * 8 + (k >> 4)) * 32 + (r & 7) * 4 + ((k & 7) >> 1)) * 4
           + ((k >> 3) & 1) * 2 + ((r >> 3) & 1);
}

// ===========================================================================
// K4/K5: fused persistent layer with per-group pipelines (unchanged R16).
// ===========================================================================
#define SM_SSUM 0
#define SM_SSQ  512
#define SM_SC   1024
#define SM_SH   1536
#define SM_A    2048
#define SM_B    (2048 + 16384)
#define GEMM_SMEM_TOTAL (2048 + 16384 + 32768)

__device__ __forceinline__ void mma_f16(float* c, const u32* a, const u32* b) {
    asm volatile(
        "mma.sync.aligned.m16n8k16.row.col.f32.f16.f16.f32 "
        "{%0,%1,%2,%3}, {%4,%5,%6,%7}, {%8,%9}, {%0,%1,%2,%3};"
        : "+f"(c[0]), "+f"(c[1]), "+f"(c[2]), "+f"(c[3])
        : "r"(a[0]), "r"(a[1]), "r"(a[2]), "r"(a[3]), "r"(b[0]), "r"(b[1]));
}

__device__ __forceinline__ void acc_u2(float4& acc, uint2 u) {
    float2 f0 = __half22float2(*(__half2*)&u.x);
    float2 f1 = __half22float2(*(__half2*)&u.y);
    acc.x += f0.x; acc.y += f0.y; acc.z += f1.x; acc.w += f1.y;
}

#define GROUP_BAR(id) asm volatile("bar.sync %0, 128;" :: "r"(id) : "memory")

template <int LAYER>
__global__ void __launch_bounds__(512, 2) fused_layer_kernel(
        const float* __restrict__ bias,
        const float* __restrict__ gamma0,  // LAYER==1: BN params of layer 0
        const float* __restrict__ beta0,
        float invN, int N, int ntiles) {
    extern __shared__ char smem[];
    float* s_sum = (float*)(smem + SM_SSUM);
    float* s_sq  = (float*)(smem + SM_SSQ);
    float* s_sc  = (float*)(smem + SM_SC);
    float* s_sh  = (float*)(smem + SM_SH);
    u32* AF = (u32*)(smem + SM_A);
    u32* BF = (u32*)(smem + SM_B);

    int tid = threadIdx.x, wid = tid >> 5, lane = tid & 31;
    const u32* base = LAYER ? g_h16 : g_x16;
    u32* outbuf     = LAYER ? g_x16 : g_h16;

    if (tid < 128) {
        s_sum[tid] = 0.f; s_sq[tid] = 0.f;
        if (LAYER == 1) {
            float m = g_sum[0][tid] * invN;
            float var = g_sq[0][tid] * invN - m * m;
            float s = gamma0[tid] * rsqrtf(var + 1e-5f);
            s_sc[tid] = s;
            s_sh[tid] = beta0[tid] - m * s;
        }
    }
    {
        const float4* sf = (const float4*)g_wf[LAYER];
        float4* df = (float4*)BF;
        for (int p = tid; p < 2048; p += 512) df[p] = sf[p];
    }
    __syncthreads();

    float4 sc4, sh4;
    if (LAYER == 1) {
        sc4 = *(const float4*)&s_sc[lane * 4];
        sh4 = *(const float4*)&s_sh[lane * 4];
    }

    int wm = wid & 3, wn = wid >> 2;
    int barid = 1 + wm;
    int g = lane >> 2, tig = lane & 3;

    for (int tile = blockIdx.x; tile < ntiles; tile += gridDim.x) {
        int row0 = tile * 64;

#pragma unroll 1
        for (int ni = 0; ni < 4; ni++) {
            int r = wm * 16 + wn * 4 + ni;
            int gr = row0 + r;
            float4 acc = make_float4(0.f, 0.f, 0.f, 0.f);
            float cnt = 0.f;
            if (gr < N) {
                acc_u2(acc, *(const uint2*)(base + (size_t)gr * 64 + lane * 2));
                int start = g_rowptr[gr];
                int end   = g_rowptr[gr + 1];
                cnt = (float)(end - start + 1);
                for (int j0 = start; j0 < end; j0 += 32) {
                    int n = end - j0; if (n > 32) n = 32;
                    int myIdx = (lane < n) ? g_adj[j0 + lane] : 0;
                    int k = 0;
                    for (; k + 8 <= n; k += 8) {
                        uint2 u[8];
#pragma unroll
                        for (int q = 0; q < 8; q++) {
                            int nb = __shfl_sync(0xffffffffu, myIdx, k + q);
                            u[q] = *(const uint2*)(base + (size_t)nb * 64 + lane * 2);
                        }
#pragma unroll
                        for (int q = 0; q < 8; q++) acc_u2(acc, u[q]);
                    }
                    for (; k < n; k++) {
                        int nb = __shfl_sync(0xffffffffu, myIdx, k);
                        acc_u2(acc, *(const uint2*)(base + (size_t)nb * 64 + lane * 2));
                    }
                }
            }
            float4 tv;
            if (LAYER == 1) {
                tv.x = fmaf(acc.x, sc4.x, cnt * sh4.x);
                tv.y = fmaf(acc.y, sc4.y, cnt * sh4.y);
                tv.z = fmaf(acc.z, sc4.z, cnt * sh4.z);
                tv.w = fmaf(acc.w, sc4.w, cnt * sh4.w);
            } else {
                tv = acc;
            }
            __half2 p0 = __float22half2_rn(make_float2(tv.x, tv.y));
            __half2 p1 = __float22half2_rn(make_float2(tv.z, tv.w));
            int k0 = lane * 4;
            AF[a_fragidx(r, k0)]     = *(u32*)&p0;
            AF[a_fragidx(r, k0 + 2)] = *(u32*)&p1;
        }
        GROUP_BAR(barid);

        float acc[4][4];
#pragma unroll
        for (int n = 0; n < 4; n++)
#pragma unroll
            for (int q = 0; q < 4; q++) acc[n][q] = 0.f;

#pragma unroll
        for (int kt = 0; kt < 8; kt++) {
            u32 ah[4];
            {
                int bq = ((wm * 8 + kt) * 32 + lane) * 4;
                *(uint4*)ah = *(const uint4*)(AF + bq);
            }
#pragma unroll
            for (int n = 0; n < 4; n++) {
                u32 bf[2];
                int bq = (((wn * 4 + n) * 8 + kt) * 32 + lane) * 2;
                *(uint2*)bf = *(const uint2*)(BF + bq);
                mma_f16(acc[n], ah, bf);
            }
        }

#pragma unroll
        for (int n = 0; n < 4; n++) {
            int cbase = wn * 32 + n * 8 + tig * 2;
            float2 bb = *(const float2*)(bias + cbase);
            float s0 = 0.f, s1 = 0.f, q0 = 0.f, q1 = 0.f;
            int rb = row0 + wm * 16 + g;
#pragma unroll
            for (int rh = 0; rh < 2; rh++) {
                int gr = rb + rh * 8;
                float h0 = fmaxf(acc[n][rh * 2 + 0] + bb.x, 0.f);
                float h1 = fmaxf(acc[n][rh * 2 + 1] + bb.y, 0.f);
                if (gr < N) {
                    __half2 hq = __float22half2_rn(make_float2(h0, h1));
                    outbuf[(size_t)gr * 64 + (cbase >> 1)] = *(u32*)&hq;
                    float2 hf = __half22float2(hq);
                    h0 = hf.x; h1 = hf.y;   // stats on quantized values
                    s0 += h0; s1 += h1;
                    q0 += h0 * h0; q1 += h1 * h1;
                }
            }
#pragma unroll
            for (int o = 4; o < 32; o <<= 1) {
                s0 += __shfl_xor_sync(0xffffffffu, s0, o);
                s1 += __shfl_xor_sync(0xffffffffu, s1, o);
                q0 += __shfl_xor_sync(0xffffffffu, q0, o);
                q1 += __shfl_xor_sync(0xffffffffu, q1, o);
            }
            if (g == 0) {
                atomicAdd(&s_sum[cbase], s0);
                atomicAdd(&s_sum[cbase + 1], s1);
                atomicAdd(&s_sq[cbase], q0);
                atomicAdd(&s_sq[cbase + 1], q1);
            }
        }
        GROUP_BAR(barid);
    }

    __syncthreads();
    if (tid < 128) {
        atomicAdd(&g_sum[LAYER][tid], s_sum[tid]);
        atomicAdd(&g_sq[LAYER][tid], s_sq[tid]);
    }
}

// ===========================================================================
// K6: final BN apply: out = fp16(h2) * sc + sh (reads g_x16, fp32 out).
// ===========================================================================
__global__ void __launch_bounds__(256) bn_apply_kernel(float2* __restrict__ dst,
                                                       const float* __restrict__ gamma,
                                                       const float* __restrict__ beta,
                                                       float invN, int n64) {
    __shared__ float s_sc[128], s_sh[128];
    if (threadIdx.x < 128) {
        int c = threadIdx.x;
        float m = g_sum[1][c] * invN;
        float var = g_sq[1][c] * invN - m * m;
        float s = gamma[c] * rsqrtf(var + 1e-5f);
        s_sc[c] = s;
        s_sh[c] = beta[c] - m * s;
    }
    __syncthreads();
    int i = blockIdx.x * 256 + threadIdx.x;
    if (i >= n64) return;
    int c = (i & 63) * 2;
    u32 u = g_x16[i];
    float2 v = __half22float2(*(__half2*)&u);
    float2 o;
    o.x = fmaf(v.x, s_sc[c],     s_sh[c]);
    o.y = fmaf(v.y, s_sc[c + 1], s_sh[c + 1]);
    dst[i] = o;
}

// ===========================================================================
// Launch
// ===========================================================================
extern "C" void kernel_launch(void* const* d_in, const int* in_sizes, int n_in,
                              void* d_out, int out_size) {
    const float* x    = (const float*)d_in[0];
    const void*  eidx = d_in[1];
    const float* W1   = (const float*)d_in[2];
    const float* b1   = (const float*)d_in[3];
    const float* W2   = (const float*)d_in[4];
    const float* b2   = (const float*)d_in[5];
    const float* g1   = (const float*)d_in[6];
    const float* be1  = (const float*)d_in[7];
    const float* g2   = (const float*)d_in[8];
    const float* be2  = (const float*)d_in[9];

    int N = in_sizes[0] / 128;
    int E = in_sizes[1] / 2;
    int n64 = N * 64;
    int agrid = (n64 + 255) / 256;
    int e4grid = (E + 1023) / 1024;
    int nb = (N + 1 + SCAN_B - 1) / SCAN_B;     // <= 49 blocks (co-resident)
    int ntiles = (N + 63) / 64;
    int pgrid = 296;                            // 2 CTAs/SM x 148 SMs
    if (pgrid > ntiles) pgrid = ntiles;
    int xblk = (n64 + 255) / 256;
    float invN = 1.0f / (float)N;

    cudaFuncSetAttribute(fused_layer_kernel<0>,
                         cudaFuncAttributeMaxDynamicSharedMemorySize, GEMM_SMEM_TOTAL);
    cudaFuncSetAttribute(fused_layer_kernel<1>,
                         cudaFuncAttributeMaxDynamicSharedMemorySize, GEMM_SMEM_TOTAL);

    // ---- K1: prep (W frags + x conv + globals) ∪ histogram-with-slots ----
    prep_kernel<<<64 + xblk + e4grid, 256>>>(W1, W2, x, (const int*)eidx, E, N, xblk);
    // ---- K2: scan -> rowptr (re-zeroes g_cnt) ----
    scan_kernel<<<nb, SCAN_T>>>(N);
    // ---- K3: atomic-free fill ----
    fill_kernel<<<e4grid, 256>>>(eidx, E);

    // ---- Layer 1: gather(g_x16) + GEMM + stats -> g_h16 ----
    fused_layer_kernel<0><<<pgrid, 512, GEMM_SMEM_TOTAL>>>(b1, nullptr, nullptr, invN, N, ntiles);
    // ---- Layer 2: BN0-folded gather(g_h16) + GEMM + stats -> g_x16 ----
    fused_layer_kernel<1><<<pgrid, 512, GEMM_SMEM_TOTAL>>>(b2, g1, be1, invN, N, ntiles);
    // ---- Final BN apply -> d_out ----
    bn_apply_kernel<<<agrid, 256>>>((float2*)d_out, g2, be2, invN, n64);
}